// round 4
// baseline (speedup 1.0000x reference)
#include <cuda_runtime.h>
#include <cuda_bf16.h>
#include <cstdint>

// Problem constants (from reference_code)
#define N_OUT 4096
#define N_IN  4096
#define BATCH 4096

// Dense W scratch: 4096*4096 f32 = 64 MB. __device__ global (allocation-free rule).
__device__ float g_W[(size_t)N_OUT * N_IN];

// ---------------------------------------------------------------------------
// Kernel 1: zero the dense W scratch (vectorized grid-stride)
// ---------------------------------------------------------------------------
__global__ void zero_W_kernel() {
    float4* p = reinterpret_cast<float4*>(g_W);
    const size_t n4 = (size_t)N_OUT * N_IN / 4;
    size_t i = (size_t)blockIdx.x * blockDim.x + threadIdx.x;
    size_t stride = (size_t)gridDim.x * blockDim.x;
    float4 z = make_float4(0.f, 0.f, 0.f, 0.f);
    for (; i < n4; i += stride) p[i] = z;
}

// ---------------------------------------------------------------------------
// Kernel 2: COO scatter-add into dense W (duplicates summed via atomics)
// ---------------------------------------------------------------------------
__global__ void scatter_kernel(const float* __restrict__ values,
                               const int* __restrict__ rows,
                               const int* __restrict__ cols,
                               int nnz) {
    int i = blockIdx.x * blockDim.x + threadIdx.x;
    if (i < nnz) {
        int r = rows[i];
        int c = cols[i];
        atomicAdd(&g_W[(size_t)r * N_IN + c], values[i]);
    }
}

// ---------------------------------------------------------------------------
// Kernel 3: dense GEMM  C = relu(W @ B + bias)
//   W: [N_OUT, N_IN] row-major (g_W)
//   B: [N_IN, BATCH] row-major (inputs)
//   C: [N_OUT, BATCH] row-major
// Tiling: BM=128, BN=128, BK=16, 256 threads, 8x8 per thread.
// ---------------------------------------------------------------------------
#define BM 128
#define BN 128
#define BK 16
#define TM 8
#define TN 8

__global__ __launch_bounds__(256)
void gemm_bias_relu_kernel(const float* __restrict__ B,
                           const float* __restrict__ bias,
                           float* __restrict__ C) {
    __shared__ float As[BK][BM];   // A tile stored transposed: As[k][m]
    __shared__ float Bs[BK][BN];   // Bs[k][n]

    const int tid = threadIdx.x;
    const int bm = blockIdx.y * BM;          // output row block
    const int bn = blockIdx.x * BN;          // output col block

    // 16x16 thread grid over the 128x128 tile
    const int tr = (tid >> 4) * TM;          // row offset within tile
    const int tc = (tid & 15) * TN;          // col offset within tile

    float acc[TM][TN];
    #pragma unroll
    for (int i = 0; i < TM; i++)
        #pragma unroll
        for (int j = 0; j < TN; j++)
            acc[i][j] = 0.f;

    const float* Ab = g_W + (size_t)bm * N_IN;
    const float* Bb = B + bn;

    for (int k0 = 0; k0 < N_IN; k0 += BK) {
        // Load A tile: 128 rows x 16 k -> 512 float4, 2 per thread.
        // float4 index i: row = i/4, k-chunk = (i%4)*4. Stored transposed.
        #pragma unroll
        for (int l = 0; l < 2; l++) {
            int i = tid + l * 256;
            int row = i >> 2;
            int kc = (i & 3) << 2;
            float4 v = *reinterpret_cast<const float4*>(
                Ab + (size_t)row * N_IN + k0 + kc);
            As[kc + 0][row] = v.x;
            As[kc + 1][row] = v.y;
            As[kc + 2][row] = v.z;
            As[kc + 3][row] = v.w;
        }
        // Load B tile: 16 k-rows x 128 cols -> 512 float4, 2 per thread.
        #pragma unroll
        for (int l = 0; l < 2; l++) {
            int i = tid + l * 256;
            int row = i >> 5;            // 32 float4 per row
            int col = (i & 31) << 2;
            *reinterpret_cast<float4*>(&Bs[row][col]) =
                *reinterpret_cast<const float4*>(
                    Bb + (size_t)(k0 + row) * BATCH + col);
        }
        __syncthreads();

        #pragma unroll
        for (int k = 0; k < BK; k++) {
            float a[TM], b[TN];
            #pragma unroll
            for (int i = 0; i < TM; i++) a[i] = As[k][tr + i];
            #pragma unroll
            for (int j = 0; j < TN; j++) b[j] = Bs[k][tc + j];
            #pragma unroll
            for (int i = 0; i < TM; i++)
                #pragma unroll
                for (int j = 0; j < TN; j++)
                    acc[i][j] = fmaf(a[i], b[j], acc[i][j]);
        }
        __syncthreads();
    }

    // Epilogue: bias + relu, vectorized stores (8 contiguous floats/row/thread)
    #pragma unroll
    for (int i = 0; i < TM; i++) {
        const int row = bm + tr + i;
        const float bv = bias[row];
        float* Crow = C + (size_t)row * BATCH + bn + tc;
        #pragma unroll
        for (int j = 0; j < TN; j += 4) {
            float4 v;
            v.x = fmaxf(acc[i][j + 0] + bv, 0.f);
            v.y = fmaxf(acc[i][j + 1] + bv, 0.f);
            v.z = fmaxf(acc[i][j + 2] + bv, 0.f);
            v.w = fmaxf(acc[i][j + 3] + bv, 0.f);
            *reinterpret_cast<float4*>(Crow + j) = v;
        }
    }
}

// ---------------------------------------------------------------------------
// kernel_launch
// Inputs (metadata order): inputs f32 [N_IN*BATCH], values f32 [NNZ],
//                          biases f32 [N_OUT], rows i32 [NNZ], cols i32 [NNZ]
// Output: f32 [N_OUT*BATCH]
// ---------------------------------------------------------------------------
extern "C" void kernel_launch(void* const* d_in, const int* in_sizes, int n_in,
                              void* d_out, int out_size) {
    const float* inputs = (const float*)d_in[0];
    const float* values = (const float*)d_in[1];
    const float* biases = (const float*)d_in[2];
    const int*   rows   = (const int*)d_in[3];
    const int*   cols   = (const int*)d_in[4];
    float* out = (float*)d_out;
    const int nnz = in_sizes[1];

    // Phase 1: zero dense W
    zero_W_kernel<<<2048, 256>>>();

    // Phase 2: COO scatter-add
    scatter_kernel<<<(nnz + 255) / 256, 256>>>(values, rows, cols, nnz);

    // Phase 3: GEMM + bias + relu
    dim3 grid(BATCH / BN, N_OUT / BM);
    gemm_bias_relu_kernel<<<grid, 256>>>(inputs, biases, out);
}

// round 8
// speedup vs baseline: 2.7692x; 2.7692x over previous
#include <cuda_runtime.h>
#include <cuda_bf16.h>
#include <cstdint>

// Problem constants
#define N_OUT 4096
#define N_IN  4096
#define BATCH 4096

// ---------------------------------------------------------------------------
// Static device scratch (allocation-free rule)
// ---------------------------------------------------------------------------
__device__ float g_W[(size_t)N_OUT * N_IN];                 // 64 MB dense W
__device__ __nv_bfloat16 g_Whi[(size_t)N_OUT * N_IN];       // 32 MB
__device__ __nv_bfloat16 g_Wlo[(size_t)N_OUT * N_IN];       // 32 MB
__device__ __nv_bfloat16 g_Bhi[(size_t)BATCH * N_IN];       // 32 MB, [n][k] K-major
__device__ __nv_bfloat16 g_Blo[(size_t)BATCH * N_IN];       // 32 MB

// ---------------------------------------------------------------------------
// Helpers (base-ISA only: cp.async sm_80, ldmatrix sm_75, mma.sync sm_80)
// ---------------------------------------------------------------------------
__device__ __forceinline__ uint32_t smem_u32(const void* p) {
    uint32_t a;
    asm("{ .reg .u64 t; cvta.to.shared.u64 t, %1; cvt.u32.u64 %0, t; }"
        : "=r"(a) : "l"(p));
    return a;
}

__device__ __forceinline__ void cp_async16(uint32_t sdst, const void* gsrc) {
    asm volatile("cp.async.cg.shared.global [%0], [%1], 16;"
                 :: "r"(sdst), "l"(gsrc) : "memory");
}
#define CP_COMMIT() asm volatile("cp.async.commit_group;" ::: "memory")
#define CP_WAIT0()  asm volatile("cp.async.wait_group 0;" ::: "memory")

__device__ __forceinline__ void ldsm_x4(uint32_t r[4], uint32_t addr) {
    asm volatile("ldmatrix.sync.aligned.m8n8.x4.shared.b16 {%0,%1,%2,%3}, [%4];"
                 : "=r"(r[0]), "=r"(r[1]), "=r"(r[2]), "=r"(r[3]) : "r"(addr));
}

__device__ __forceinline__ void mma_bf16(float d[4], const uint32_t a[4],
                                         const uint32_t b[2]) {
    asm volatile(
        "mma.sync.aligned.m16n8k16.row.col.f32.bf16.bf16.f32 "
        "{%0,%1,%2,%3}, {%4,%5,%6,%7}, {%8,%9}, {%0,%1,%2,%3};"
        : "+f"(d[0]), "+f"(d[1]), "+f"(d[2]), "+f"(d[3])
        : "r"(a[0]), "r"(a[1]), "r"(a[2]), "r"(a[3]), "r"(b[0]), "r"(b[1]));
}

// ---------------------------------------------------------------------------
// Kernel 1: zero dense W
// ---------------------------------------------------------------------------
__global__ void zero_W_kernel() {
    float4* p = reinterpret_cast<float4*>(g_W);
    const size_t n4 = (size_t)N_OUT * N_IN / 4;
    size_t i = (size_t)blockIdx.x * blockDim.x + threadIdx.x;
    size_t stride = (size_t)gridDim.x * blockDim.x;
    float4 z = make_float4(0.f, 0.f, 0.f, 0.f);
    for (; i < n4; i += stride) p[i] = z;
}

// ---------------------------------------------------------------------------
// Kernel 2: COO scatter-add
// ---------------------------------------------------------------------------
__global__ void scatter_kernel(const float* __restrict__ values,
                               const int* __restrict__ rows,
                               const int* __restrict__ cols, int nnz) {
    int i = blockIdx.x * blockDim.x + threadIdx.x;
    if (i < nnz) atomicAdd(&g_W[(size_t)rows[i] * N_IN + cols[i]], values[i]);
}

// ---------------------------------------------------------------------------
// Kernel 3: W fp32 -> (hi, lo) bf16 split
// ---------------------------------------------------------------------------
__global__ void convert_W_kernel() {
    const size_t n4 = (size_t)N_OUT * N_IN / 4;
    const float4* src = reinterpret_cast<const float4*>(g_W);
    __nv_bfloat162* hi = reinterpret_cast<__nv_bfloat162*>(g_Whi);
    __nv_bfloat162* lo = reinterpret_cast<__nv_bfloat162*>(g_Wlo);
    size_t i = (size_t)blockIdx.x * blockDim.x + threadIdx.x;
    size_t stride = (size_t)gridDim.x * blockDim.x;
    for (; i < n4; i += stride) {
        float4 w = src[i];
        __nv_bfloat16 hx = __float2bfloat16_rn(w.x);
        __nv_bfloat16 hy = __float2bfloat16_rn(w.y);
        __nv_bfloat16 hz = __float2bfloat16_rn(w.z);
        __nv_bfloat16 hw = __float2bfloat16_rn(w.w);
        __nv_bfloat16 lx = __float2bfloat16_rn(w.x - __bfloat162float(hx));
        __nv_bfloat16 ly = __float2bfloat16_rn(w.y - __bfloat162float(hy));
        __nv_bfloat16 lz = __float2bfloat16_rn(w.z - __bfloat162float(hz));
        __nv_bfloat16 lw = __float2bfloat16_rn(w.w - __bfloat162float(hw));
        hi[2 * i]     = __nv_bfloat162(hx, hy);
        hi[2 * i + 1] = __nv_bfloat162(hz, hw);
        lo[2 * i]     = __nv_bfloat162(lx, ly);
        lo[2 * i + 1] = __nv_bfloat162(lz, lw);
    }
}

// ---------------------------------------------------------------------------
// Kernel 4: inputs [k][n] fp32 -> transposed bf16 (hi, lo) [n][k]
// ---------------------------------------------------------------------------
__global__ void convert_B_kernel(const float* __restrict__ inp) {
    __shared__ float ts[32][33];
    int n0 = blockIdx.x * 32, k0 = blockIdx.y * 32;
    int tx = threadIdx.x, ty = threadIdx.y;   // 32 x 8
    #pragma unroll
    for (int r = ty; r < 32; r += 8)
        ts[r][tx] = inp[(size_t)(k0 + r) * BATCH + n0 + tx];
    __syncthreads();
    #pragma unroll
    for (int r = ty; r < 32; r += 8) {
        float v = ts[tx][r];
        __nv_bfloat16 h = __float2bfloat16_rn(v);
        __nv_bfloat16 l = __float2bfloat16_rn(v - __bfloat162float(h));
        size_t o = (size_t)(n0 + r) * N_IN + k0 + tx;
        g_Bhi[o] = h;
        g_Blo[o] = l;
    }
}

// ---------------------------------------------------------------------------
// Kernel 5: mma.sync split-bf16 GEMM + bias + relu
//   128x128x32 CTA tile, 8 warps (warp tile 64x32), double-buffered cp.async.
//   D = Ahi*Bhi + Ahi*Blo + Alo*Bhi (fp32 accum).
// ---------------------------------------------------------------------------
#define BM 128
#define BN 128
#define BK 32
#define NCH (N_IN / BK)        // 128 chunks
#define ROWB 80                // padded row stride (40 bf16): conflict-free ldmatrix
#define TILEB (128 * ROWB)     // 10240 B per tile
#define STAGEB (4 * TILEB)     // Ahi, Alo, Bhi, Blo
#define OFF_AH 0
#define OFF_AL TILEB
#define OFF_BH (2 * TILEB)
#define OFF_BL (3 * TILEB)
#define GEMM_SMEM (2 * STAGEB) // 81920 B

__device__ __forceinline__ void load_chunk(uint32_t sb, int s, int c,
                                           int bm, int bn, int tid) {
    const size_t kof = (size_t)c * BK;
    const __nv_bfloat16* ah = g_Whi + (size_t)bm * N_IN + kof;
    const __nv_bfloat16* al = g_Wlo + (size_t)bm * N_IN + kof;
    const __nv_bfloat16* bh = g_Bhi + (size_t)bn * N_IN + kof;
    const __nv_bfloat16* bl = g_Blo + (size_t)bn * N_IN + kof;
    const uint32_t st = sb + s * STAGEB;
    #pragma unroll
    for (int l = 0; l < 2; l++) {
        int i = tid + l * 256;
        int row = i >> 2;
        int kc = i & 3;
        size_t go = (size_t)row * N_IN + kc * 8;
        uint32_t so = row * ROWB + kc * 16;
        cp_async16(st + OFF_AH + so, ah + go);
        cp_async16(st + OFF_AL + so, al + go);
        cp_async16(st + OFF_BH + so, bh + go);
        cp_async16(st + OFF_BL + so, bl + go);
    }
}

__global__ __launch_bounds__(256, 2)
void gemm_mma_kernel(const float* __restrict__ bias, float* __restrict__ C) {
    extern __shared__ char smem[];
    const uint32_t sb = smem_u32(smem);
    const int tid = threadIdx.x;
    const int wid = tid >> 5, lane = tid & 31;
    const int warp_m = wid >> 2;          // 0..1  -> 64-row slab
    const int warp_n = wid & 3;           // 0..3  -> 32-col slab
    const int bm = blockIdx.y * BM, bn = blockIdx.x * BN;

    float acc[4][4][4];
    #pragma unroll
    for (int mt = 0; mt < 4; mt++)
        #pragma unroll
        for (int nt = 0; nt < 4; nt++)
            #pragma unroll
            for (int r = 0; r < 4; r++) acc[mt][nt][r] = 0.f;

    // Per-lane ldmatrix byte offsets within a stage.
    // A (m16 x k16): lanes 0-15 -> rows 0-15 at k0; lanes 16-31 -> rows at k0+8.
    const uint32_t aRow = warp_m * 64 + (lane & 15);
    const uint32_t aOff = aRow * ROWB + (lane >> 4) * 16;
    // B x4 covers 2 n-tiles (n16 x k16): matrix = lane>>3;
    //   n = (lane>>4)*8 + (lane&7), k = ((lane>>3)&1)*8
    const uint32_t bRow = warp_n * 32 + ((lane >> 4) & 1) * 8 + (lane & 7);
    const uint32_t bOff = bRow * ROWB + ((lane >> 3) & 1) * 16;

    // Prologue
    load_chunk(sb, 0, 0, bm, bn, tid);
    CP_COMMIT();

    for (int c = 0; c < NCH; c++) {
        const int s = c & 1;
        CP_WAIT0();
        __syncthreads();
        if (c + 1 < NCH) {
            load_chunk(sb, s ^ 1, c + 1, bm, bn, tid);
            CP_COMMIT();
        }
        const uint32_t base = sb + s * STAGEB;
        #pragma unroll
        for (int ks = 0; ks < 2; ks++) {
            const uint32_t ko = ks * 32;   // 16 bf16 = 32 B
            uint32_t ah[4][4], bh[2][4], bl[2][4];
            #pragma unroll
            for (int mt = 0; mt < 4; mt++)
                ldsm_x4(ah[mt], base + OFF_AH + aOff + mt * (16 * ROWB) + ko);
            #pragma unroll
            for (int j = 0; j < 2; j++)
                ldsm_x4(bh[j], base + OFF_BH + bOff + j * (16 * ROWB) + ko);
            #pragma unroll
            for (int j = 0; j < 2; j++)
                ldsm_x4(bl[j], base + OFF_BL + bOff + j * (16 * ROWB) + ko);
            #pragma unroll
            for (int mt = 0; mt < 4; mt++)
                #pragma unroll
                for (int nt = 0; nt < 4; nt++)
                    mma_bf16(acc[mt][nt], ah[mt], &bh[nt >> 1][(nt & 1) * 2]);
            #pragma unroll
            for (int mt = 0; mt < 4; mt++)
                #pragma unroll
                for (int nt = 0; nt < 4; nt++)
                    mma_bf16(acc[mt][nt], ah[mt], &bl[nt >> 1][(nt & 1) * 2]);
            uint32_t al[4][4];
            #pragma unroll
            for (int mt = 0; mt < 4; mt++)
                ldsm_x4(al[mt], base + OFF_AL + aOff + mt * (16 * ROWB) + ko);
            #pragma unroll
            for (int mt = 0; mt < 4; mt++)
                #pragma unroll
                for (int nt = 0; nt < 4; nt++)
                    mma_bf16(acc[mt][nt], al[mt], &bh[nt >> 1][(nt & 1) * 2]);
        }
        __syncthreads();
    }

    // Epilogue: bias + relu. acc tile layout: d0,d1 = row gid cols 2tig,2tig+1;
    // d2,d3 = row gid+8.
    const int gid = lane >> 2, tig = lane & 3;
    #pragma unroll
    for (int mt = 0; mt < 4; mt++) {
        const int r0 = bm + warp_m * 64 + mt * 16 + gid;
        const int r1 = r0 + 8;
        const float bv0 = bias[r0], bv1 = bias[r1];
        #pragma unroll
        for (int nt = 0; nt < 4; nt++) {
            const int col = bn + warp_n * 32 + nt * 8 + tig * 2;
            float2 v0, v1;
            v0.x = fmaxf(acc[mt][nt][0] + bv0, 0.f);
            v0.y = fmaxf(acc[mt][nt][1] + bv0, 0.f);
            v1.x = fmaxf(acc[mt][nt][2] + bv1, 0.f);
            v1.y = fmaxf(acc[mt][nt][3] + bv1, 0.f);
            *reinterpret_cast<float2*>(C + (size_t)r0 * BATCH + col) = v0;
            *reinterpret_cast<float2*>(C + (size_t)r1 * BATCH + col) = v1;
        }
    }
}

// ---------------------------------------------------------------------------
// kernel_launch
// ---------------------------------------------------------------------------
extern "C" void kernel_launch(void* const* d_in, const int* in_sizes, int n_in,
                              void* d_out, int out_size) {
    const float* inputs = (const float*)d_in[0];
    const float* values = (const float*)d_in[1];
    const float* biases = (const float*)d_in[2];
    const int*   rows   = (const int*)d_in[3];
    const int*   cols   = (const int*)d_in[4];
    float* out = (float*)d_out;
    const int nnz = in_sizes[1];

    cudaFuncSetAttribute(gemm_mma_kernel,
                         cudaFuncAttributeMaxDynamicSharedMemorySize, GEMM_SMEM);

    zero_W_kernel<<<2048, 256>>>();
    scatter_kernel<<<(nnz + 255) / 256, 256>>>(values, rows, cols, nnz);
    convert_W_kernel<<<2048, 256>>>();
    convert_B_kernel<<<dim3(BATCH / 32, N_IN / 32), dim3(32, 8)>>>(inputs);
    gemm_mma_kernel<<<dim3(BATCH / BN, N_OUT / BM), 256, GEMM_SMEM>>>(biases, out);
}